// round 13
// baseline (speedup 1.0000x reference)
#include <cuda_runtime.h>
#include <cuda_bf16.h>
#include <cstdint>

// SupConLoss: N=8192 embeddings (C=128, L2-normalized), logits = X X^T / T.
// TS-mode tcgen05 syrk (A in TMEM, hi/lo bf16 split) over the upper triangle;
// 3-deep bulk-DMA B ring; workers pipeline LDTM ahead of the exp epilogue.
// Row + (symmetry) column sums per off-diag tile. P via per-class sums.

#define Nn 8192
#define TILE 128
#define TRI_TILES 2080               // 64*65/2
#define NBLK_TC 148
#define NTHREADS 288                 // 8 worker warps + 1 issuer warp
#define INV_T 14.285714285714285714f
#define PSCALE 4.5398161f            // sqrt(INV_T * log2(e))

#if !defined(__CUDA_ARCH__)
#  define TC_OK 1
#elif defined(__CUDA_ARCH_FEAT_SM103_ALL) || defined(__CUDA_ARCH_FEAT_SM100_ALL) || \
      defined(__CUDA_ARCH_FEAT_SM101_ALL) || defined(__CUDA_ARCH_FAMILY_SPECIFIC__) || \
      defined(__CUDA_ARCH_SPECIFIC__)
#  define TC_OK 1
#else
#  define TC_OK 0
#endif

__device__ uint4 g_hi[Nn * 128 / 8];   // 2 MB blocked SW128-swizzled bf16 tiles
__device__ uint4 g_lo[Nn * 128 / 8];
__device__ float g_S[Nn];
__device__ float g_P[Nn];
__device__ float g_C[4 * 128];
__device__ int   g_lab[Nn];
__device__ int   g_hist[4];

__device__ __forceinline__ uint32_t smem_u32(const void* p) {
    uint32_t a;
    asm("{ .reg .u64 t; cvta.to.shared.u64 t, %1; cvt.u32.u64 %0, t; }" : "=r"(a) : "l"(p));
    return a;
}
__device__ __forceinline__ uint32_t elect_one() {
    uint32_t pred;
    asm volatile("{ .reg .pred p; elect.sync _|p, 0xFFFFFFFF; selp.b32 %0, 1, 0, p; }" : "=r"(pred));
    return pred;
}
#define MBARRIER_INIT(mb, c) \
    asm volatile("mbarrier.init.shared.b64 [%0], %1;" :: "r"((uint32_t)(mb)), "r"((uint32_t)(c)) : "memory")
#define MBARRIER_INVAL(mb) \
    asm volatile("mbarrier.inval.shared.b64 [%0];" :: "r"((uint32_t)(mb)) : "memory")
#define MBARRIER_ARRIVE(mb) \
    asm volatile("mbarrier.arrive.release.cta.shared::cta.b64 _, [%0];" :: "r"((uint32_t)(mb)) : "memory")
#define MBARRIER_EXPECT_TX(mb, bytes) \
    asm volatile("mbarrier.arrive.expect_tx.shared.b64 _, [%0], %1;" \
                 :: "r"((uint32_t)(mb)), "r"((uint32_t)(bytes)) : "memory")
#define MBARRIER_WAIT_PARITY(mb, ph) do {                                          \
    uint32_t _m = (uint32_t)(mb), _p = (uint32_t)(ph), _d;                         \
    asm volatile("{ .reg .pred p; mbarrier.try_wait.parity.acquire.cta.shared::cta.b64 p, [%1], %2; selp.b32 %0, 1, 0, p; }" \
                 : "=r"(_d) : "r"(_m), "r"(_p) : "memory");                        \
    if (!_d) {                                                                     \
        asm volatile("{ .reg .pred P1; WL_%=: mbarrier.try_wait.parity.acquire.cta.shared::cta.b64 P1, [%0], %1, 0x989680; @P1 bra.uni WD_%=; bra.uni WL_%=; WD_%=: }" \
                     :: "r"(_m), "r"(_p) : "memory");                              \
    } } while (0)

#if TC_OK
#define TCGEN05_ALLOC(sa, n) \
    asm volatile("tcgen05.alloc.cta_group::1.sync.aligned.shared::cta.b32 [%0], %1;" \
                 :: "r"((uint32_t)(sa)), "r"((uint32_t)(n)) : "memory")
#define TCGEN05_DEALLOC(t, n) \
    asm volatile("tcgen05.dealloc.cta_group::1.sync.aligned.b32 %0, %1;" :: "r"(t), "r"((uint32_t)(n)))
#define TCGEN05_RELINQ() \
    asm volatile("tcgen05.relinquish_alloc_permit.cta_group::1.sync.aligned;")
#define TCGEN05_COMMIT(mb) \
    asm volatile("tcgen05.commit.cta_group::1.mbarrier::arrive::one.shared::cluster.b64 [%0];" \
                 :: "r"((uint32_t)(mb)) : "memory")
#define TCGEN05_WAIT_LD()      asm volatile("tcgen05.wait::ld.sync.aligned;" ::: "memory")
#define TCGEN05_WAIT_ST()      asm volatile("tcgen05.wait::st.sync.aligned;" ::: "memory")
#define TCGEN05_FENCE_BEFORE() asm volatile("tcgen05.fence::before_thread_sync;" ::: "memory")
#define TCGEN05_FENCE_AFTER()  asm volatile("tcgen05.fence::after_thread_sync;" ::: "memory")
#define TCGEN05_LD_X32(r, a) \
    asm volatile("tcgen05.ld.sync.aligned.32x32b.x32.b32 " \
        "{%0,%1,%2,%3,%4,%5,%6,%7,%8,%9,%10,%11,%12,%13,%14,%15," \
        "%16,%17,%18,%19,%20,%21,%22,%23,%24,%25,%26,%27,%28,%29,%30,%31}, [%32];" \
        : "=r"((r)[0]),"=r"((r)[1]),"=r"((r)[2]),"=r"((r)[3]),"=r"((r)[4]),"=r"((r)[5]),"=r"((r)[6]),"=r"((r)[7]), \
          "=r"((r)[8]),"=r"((r)[9]),"=r"((r)[10]),"=r"((r)[11]),"=r"((r)[12]),"=r"((r)[13]),"=r"((r)[14]),"=r"((r)[15]), \
          "=r"((r)[16]),"=r"((r)[17]),"=r"((r)[18]),"=r"((r)[19]),"=r"((r)[20]),"=r"((r)[21]),"=r"((r)[22]),"=r"((r)[23]), \
          "=r"((r)[24]),"=r"((r)[25]),"=r"((r)[26]),"=r"((r)[27]),"=r"((r)[28]),"=r"((r)[29]),"=r"((r)[30]),"=r"((r)[31]) \
        : "r"(a))
#define TCGEN05_ST_X64(a, r) \
    asm volatile("tcgen05.st.sync.aligned.32x32b.x64.b32 [%0], " \
        "{%1,%2,%3,%4,%5,%6,%7,%8,%9,%10,%11,%12,%13,%14,%15,%16," \
        "%17,%18,%19,%20,%21,%22,%23,%24,%25,%26,%27,%28,%29,%30,%31,%32," \
        "%33,%34,%35,%36,%37,%38,%39,%40,%41,%42,%43,%44,%45,%46,%47,%48," \
        "%49,%50,%51,%52,%53,%54,%55,%56,%57,%58,%59,%60,%61,%62,%63,%64};" \
        :: "r"(a), \
           "r"((r)[0]),"r"((r)[1]),"r"((r)[2]),"r"((r)[3]),"r"((r)[4]),"r"((r)[5]),"r"((r)[6]),"r"((r)[7]), \
           "r"((r)[8]),"r"((r)[9]),"r"((r)[10]),"r"((r)[11]),"r"((r)[12]),"r"((r)[13]),"r"((r)[14]),"r"((r)[15]), \
           "r"((r)[16]),"r"((r)[17]),"r"((r)[18]),"r"((r)[19]),"r"((r)[20]),"r"((r)[21]),"r"((r)[22]),"r"((r)[23]), \
           "r"((r)[24]),"r"((r)[25]),"r"((r)[26]),"r"((r)[27]),"r"((r)[28]),"r"((r)[29]),"r"((r)[30]),"r"((r)[31]), \
           "r"((r)[32]),"r"((r)[33]),"r"((r)[34]),"r"((r)[35]),"r"((r)[36]),"r"((r)[37]),"r"((r)[38]),"r"((r)[39]), \
           "r"((r)[40]),"r"((r)[41]),"r"((r)[42]),"r"((r)[43]),"r"((r)[44]),"r"((r)[45]),"r"((r)[46]),"r"((r)[47]), \
           "r"((r)[48]),"r"((r)[49]),"r"((r)[50]),"r"((r)[51]),"r"((r)[52]),"r"((r)[53]),"r"((r)[54]),"r"((r)[55]), \
           "r"((r)[56]),"r"((r)[57]),"r"((r)[58]),"r"((r)[59]),"r"((r)[60]),"r"((r)[61]),"r"((r)[62]),"r"((r)[63]) \
        : "memory")
#define BULK_G2S(dst, src, size, mb) \
    asm volatile("cp.async.bulk.shared::cluster.global.mbarrier::complete_tx::bytes [%0], [%1], %2, [%3];" \
                 :: "r"((uint32_t)(dst)), "l"(src), "r"((uint32_t)(size)), "r"((uint32_t)(mb)) : "memory")

static constexpr uint64_t SMEM_DESC_BASE_SW128 =
    (uint64_t(2) << 61) | (uint64_t(1) << 46) | (uint64_t(64) << 32) | (uint64_t(1) << 16);
#define MAKE_DESC(addr) (SMEM_DESC_BASE_SW128 | ((uint64_t)((addr) >> 4) & 0x3FFF))

#define MMA_IDESC 0x08200490u   // F32 d, BF16 a/b, M=128, N=128 (TS & SS share idesc)
static __device__ __forceinline__ void mma_ts(uint32_t d, uint32_t a_tmem, uint64_t b, uint32_t en) {
    asm volatile("{ .reg .pred p; setp.ne.u32 p, %4, 0;\n\t"
        "tcgen05.mma.cta_group::1.kind::f16 [%0], [%1], %2, %3, {%5,%5,%5,%5}, p; }"
        :: "r"(d), "r"(a_tmem), "l"(b), "r"(MMA_IDESC), "r"(en), "r"(0u) : "memory");
}
#endif  // TC_OK

// ---- smem: 3 B buffers (hi+lo) + control ----
#define OFF_B(q)  ((q) * 65536)          // hi at +0, lo at +32768
#define OFF_TP    196608
#define OFF_FULL0 196624
#define OFF_FULL1 196632
#define OFF_FREE0 196640
#define OFF_FREE1 196648
#define OFF_CPMB  196656
#define SMEM_SZ   196672
// TMEM: D0 @0 (128 cols), D1 @128, A_hi @256 (64), A_lo @320 (64)

__global__ void k_zero() {
    int i = blockIdx.x * 256 + threadIdx.x;
    if (i < Nn) g_S[i] = 0.f;
    if (i < 512) g_C[i] = 0.f;
    if (i < 4) g_hist[i] = 0;
}

// fp32 [B=4,V=2,C=128,HW=1024], PRE-SCALED by sqrt(EX2C) -> bf16 hi/lo,
// blocked SW128 tile format (16 atom-rows x 2 atom-cols per 128-row band).
__global__ void k_prep(const float* __restrict__ f) {
    int idx = blockIdx.x * 256 + threadIdx.x;   // 524288
    int n = idx & 8191;
    int j = idx >> 13;
    int vb = n >> 10, hw = n & 1023;
    int v = vb >> 2, b = vb & 3;
    const float* base = f + b * 262144 + v * 131072 + hw;
    float x0 = base[(2 * j) * 1024] * PSCALE;
    float x1 = base[(2 * j + 1) * 1024] * PSCALE;
    __nv_bfloat16 h0 = __float2bfloat16(x0);
    __nv_bfloat16 h1 = __float2bfloat16(x1);
    __nv_bfloat16 l0 = __float2bfloat16(x0 - __bfloat162float(h0));
    __nv_bfloat16 l1 = __float2bfloat16(x1 - __bfloat162float(h1));
    uint32_t hp = (uint32_t)__bfloat16_as_ushort(h0) | ((uint32_t)__bfloat16_as_ushort(h1) << 16);
    uint32_t lp = (uint32_t)__bfloat16_as_ushort(l0) | ((uint32_t)__bfloat16_as_ushort(l1) << 16);
    int band = n >> 7, r = n & 127, k = 2 * j;
    int atom = (r >> 3) + (k >> 6) * 16;
    uint32_t byte = atom * 1024 + (r & 7) * 128 + (k & 63) * 2;
    uint32_t sw = byte ^ ((byte >> 3) & 0x70);  // SW128
    uint32_t w = band * 8192 + (sw >> 2);
    ((uint32_t*)g_hi)[w] = hp;
    ((uint32_t*)g_lo)[w] = lp;
}

__global__ void k_lab(const int* __restrict__ labels) {
    int n = blockIdx.x * 256 + threadIdx.x;
    if (n >= Nn) return;
    int vb = n >> 10;
    int v = vb >> 2, b = vb & 3;
    int L = labels[b * 2048 + v * 1024 + (n & 1023)];
    g_lab[n] = L;
    atomicAdd(&g_hist[L], 1);
}

__global__ void k_csum(const float* __restrict__ f) {
    int bid = blockIdx.x;
    int vb = bid >> 7, c = bid & 127;
    int v = vb >> 2, b = vb & 3;
    int tid = threadIdx.x;
    float4 x = ((const float4*)(f + b * 262144 + v * 131072 + c * 1024))[tid];
    int4  l = ((const int4*)(g_lab + vb * 1024))[tid];
    float s[4] = {0.f, 0.f, 0.f, 0.f};
    s[l.x] += x.x; s[l.y] += x.y; s[l.z] += x.z; s[l.w] += x.w;
    #pragma unroll
    for (int q = 0; q < 4; q++) {
        float r = s[q];
        #pragma unroll
        for (int o = 16; o; o >>= 1) r += __shfl_xor_sync(0xffffffffu, r, o);
        if ((tid & 31) == 0 && r != 0.f) atomicAdd(&g_C[q * 128 + c], r);
    }
}

__global__ void k_dotp(const float* __restrict__ f) {
    __shared__ float sC[512];
    int tid = threadIdx.x;
    int n = blockIdx.x * 256 + tid;
    int vb = n >> 10, hw = n & 1023;
    int v = vb >> 2, b = vb & 3;
    ((float2*)sC)[tid] = ((const float2*)g_C)[tid];
    __syncthreads();
    const float* base = f + b * 262144 + v * 131072 + hw;
    const float* C = sC + g_lab[n] * 128;
    float acc = 0.f;
    #pragma unroll 16
    for (int c = 0; c < 128; c++) acc = fmaf(base[c * 1024], C[c], acc);
    g_P[n] = acc - 1.f;
}

#if TC_OK
// Load A band from blocked layout directly (16B-granular unswizzle: unit^=r&7)
// into TMEM via tcgen05.st.x64. Threads 0..127 only (rows).
static __device__ __forceinline__ void load_A_tmem(int band, uint32_t tA_hi, uint32_t tA_lo, int tid) {
    if (tid < 128) {
        int r = tid;
        uint32_t woff = (uint32_t)(r >> 5) << 21;
        uint32_t a[64];
        #pragma unroll
        for (int ac = 0; ac < 2; ac++)
            #pragma unroll
            for (int u = 0; u < 8; u++) {
                int w = band * 8192 + ((r >> 3) + ac * 16) * 256 + (r & 7) * 32 + (u ^ (r & 7)) * 4;
                uint4 v = ((const uint4*)g_hi)[w >> 2];
                a[ac * 32 + u * 4 + 0] = v.x; a[ac * 32 + u * 4 + 1] = v.y;
                a[ac * 32 + u * 4 + 2] = v.z; a[ac * 32 + u * 4 + 3] = v.w;
            }
        TCGEN05_ST_X64(tA_hi + woff, a);
        #pragma unroll
        for (int ac = 0; ac < 2; ac++)
            #pragma unroll
            for (int u = 0; u < 8; u++) {
                int w = band * 8192 + ((r >> 3) + ac * 16) * 256 + (r & 7) * 32 + (u ^ (r & 7)) * 4;
                uint4 v = ((const uint4*)g_lo)[w >> 2];
                a[ac * 32 + u * 4 + 0] = v.x; a[ac * 32 + u * 4 + 1] = v.y;
                a[ac * 32 + u * 4 + 2] = v.z; a[ac * 32 + u * 4 + 3] = v.w;
            }
        TCGEN05_ST_X64(tA_lo + woff, a);
        TCGEN05_WAIT_ST();
        TCGEN05_FENCE_BEFORE();
    }
}

// fold 32 lane-local values down to per-lane column sums (R11-proven pattern)
static __device__ __forceinline__ void fold32(float* e, int lid) {
    #pragma unroll
    for (int st = 0; st < 5; st++) {
        int k = 1 << st;
        int half = 32 >> (st + 1);
        int side = (lid >> st) & 1;
        #pragma unroll
        for (int j = 0; j < 16; j++) {
            if (j < half) {
                float keep = side ? e[2 * j + 1] : e[2 * j];
                float give = side ? e[2 * j] : e[2 * j + 1];
                float recv = __shfl_xor_sync(0xffffffffu, give, k);
                e[j] = keep + recv;
            }
        }
    }
}
#endif  // TC_OK

// ---- warp-specialized TS-mode tcgen05 main ----
__global__ __launch_bounds__(NTHREADS, 1) __cluster_dims__(1, 1, 1) void k_main_tc() {
#if TC_OK
    extern __shared__ char smc[];
    uint32_t sb = smem_u32(smc);
    int tid = threadIdx.x, wid = tid >> 5, lid = tid & 31;

    if (wid == 8) TCGEN05_ALLOC(sb + OFF_TP, 512);
    else          TCGEN05_RELINQ();
    __syncthreads();
    uint32_t tbase;
    asm volatile("ld.shared.b32 %0, [%1];" : "=r"(tbase) : "r"(sb + OFF_TP));
    uint32_t tA_hi = tbase + 256, tA_lo = tbase + 320;
    if (tid == 0) {
        MBARRIER_INIT(sb + OFF_FULL0, 1);
        MBARRIER_INIT(sb + OFF_FULL1, 1);
        MBARRIER_INIT(sb + OFF_FREE0, 256);
        MBARRIER_INIT(sb + OFF_FREE1, 256);
        MBARRIER_INIT(sb + OFF_CPMB, 1);
    }
    __syncthreads();

    const uint32_t KOFF[8] = {0, 2, 4, 6, 1024, 1026, 1028, 1030};  // 16B units

    int s0 = (int)(((long long)blockIdx.x * TRI_TILES) / NBLK_TC);
    int s1 = (int)(((long long)(blockIdx.x + 1) * TRI_TILES) / NBLK_TC);
    int rt0 = 0;
    while ((rt0 + 1) * 64 - ((rt0 + 1) * rt0) / 2 <= s0) rt0++;
    int ct0 = rt0 + (s0 - (rt0 * 64 - (rt0 * (rt0 - 1)) / 2));

    // prologue: A(rt0) -> TMEM (threads 0..127), then sync
    load_A_tmem(rt0, tA_hi, tA_lo, tid);
    __syncthreads();

    if (wid == 8) {
        // ---------------- issuer warp ----------------
        int cp = 0, fr[2] = {0, 0};
        int rt = rt0, ct = ct0, curA = rt0;

        if (elect_one()) {      // DMA for B(s0)
            MBARRIER_EXPECT_TX(sb + OFF_CPMB, 65536);
            BULK_G2S(sb + OFF_B(s0 % 3), (const char*)g_hi + ct * 32768, 32768, sb + OFF_CPMB);
            BULK_G2S(sb + OFF_B(s0 % 3) + 32768, (const char*)g_lo + ct * 32768, 32768, sb + OFF_CPMB);
        }

        for (int s = s0; s < s1; s++) {
            int b2 = s & 1, b3 = s % 3, m = s - s0;
            if (rt != curA) {                // band change: workers rewrite A TMEM
                asm volatile("bar.sync 0, %0;" :: "n"(NTHREADS) : "memory");
                asm volatile("bar.sync 1, %0;" :: "n"(NTHREADS) : "memory");
                curA = rt;
            }
            MBARRIER_WAIT_PARITY(sb + OFF_CPMB, cp);            // B(s) in smem
            cp ^= 1;
            if (m >= 2) {                    // D reuse AND B-ring reuse gate
                MBARRIER_WAIT_PARITY(sb + (b2 ? OFF_FREE1 : OFF_FREE0), fr[b2]);
                fr[b2] ^= 1;
            }
            TCGEN05_FENCE_AFTER();
            if (elect_one()) {
                uint32_t dtm = tbase + b2 * 128;
                uint64_t bH = MAKE_DESC(sb + OFF_B(b3));
                uint64_t bL = MAKE_DESC(sb + OFF_B(b3) + 32768);
                #pragma unroll
                for (int ks = 0; ks < 8; ks++) mma_ts(dtm, tA_hi + ks * 8, bH + KOFF[ks], ks > 0);
                #pragma unroll
                for (int ks = 0; ks < 8; ks++) mma_ts(dtm, tA_hi + ks * 8, bL + KOFF[ks], 1u);
                #pragma unroll
                for (int ks = 0; ks < 8; ks++) mma_ts(dtm, tA_lo + ks * 8, bH + KOFF[ks], 1u);
                TCGEN05_COMMIT(sb + (b2 ? OFF_FULL1 : OFF_FULL0));
            }
            if (s + 1 < s1) {                // DMA B(s+1): buf (s+1)%3 free
                int nct = (ct + 1 < 64) ? ct + 1 : rt + 1;   // (FREE wait above implies chain(s-2) done)
                if (elect_one()) {
                    MBARRIER_EXPECT_TX(sb + OFF_CPMB, 65536);
                    BULK_G2S(sb + OFF_B((s + 1) % 3), (const char*)g_hi + nct * 32768, 32768, sb + OFF_CPMB);
                    BULK_G2S(sb + OFF_B((s + 1) % 3) + 32768, (const char*)g_lo + nct * 32768, 32768, sb + OFF_CPMB);
                }
            }
            if (ct + 1 < 64) ct++; else { rt++; ct = rt; }
        }
    } else {
        // ---------------- worker warps (256 threads) ----------------
        int pf[2] = {0, 0};
        int colh = wid >> 2;
        int row = (wid & 3) * 32 + lid;
        int rtw = rt0, ctw = ct0, curband = rt0;
        float bufA[64], bufB[64];
        int pa_rt, pa_ct, pb_rt, pb_ct;      // coords held in bufA / bufB

        // load+transform tile (trt,tct) from D buffer b2 into dst
        #define LDTILE(b2v, trt, tct, dst) do {                                          \
            uint32_t d0[32], d1[32];                                                     \
            TCGEN05_LD_X32(d0, tbase + (b2v) * 128 + colh * 64);                         \
            TCGEN05_LD_X32(d1, tbase + (b2v) * 128 + colh * 64 + 32);                    \
            TCGEN05_WAIT_LD();                                                           \
            MBARRIER_ARRIVE(sb + ((b2v) ? OFF_FREE1 : OFF_FREE0));                       \
            bool dg = (trt) == (tct);                                                    \
            int gg = (trt) * TILE + row;                                                 \
            int jj = (tct) * TILE + colh * 64;                                           \
            _Pragma("unroll")                                                            \
            for (int c = 0; c < 32; c++) {                                               \
                float x;                                                                 \
                asm("ex2.approx.ftz.f32 %0, %1;" : "=f"(x) : "f"(__uint_as_float(d0[c])));\
                (dst)[c] = (dg && (jj + c) == gg) ? 0.f : x;                             \
            }                                                                            \
            _Pragma("unroll")                                                            \
            for (int c = 0; c < 32; c++) {                                               \
                float x;                                                                 \
                asm("ex2.approx.ftz.f32 %0, %1;" : "=f"(x) : "f"(__uint_as_float(d1[c])));\
                (dst)[32 + c] = (dg && (jj + 32 + c) == gg) ? 0.f : x;                   \
            }                                                                            \
        } while (0)

        #define ALUTILE(trt, tct, e) do {                                                \
            int gg = (trt) * TILE + row;                                                 \
            int jj = (tct) * TILE + colh * 64;                                           \
            float Ssum = 0.f;                                                            \
            _Pragma("unroll")                                                            \
            for (int c = 0; c < 64; c++) Ssum += (e)[c];                                 \
            atomicAdd(&g_S[gg], Ssum);                                                   \
            if ((trt) != (tct)) {                                                        \
                fold32((e), lid);                                                        \
                atomicAdd(&g_S[jj + lid], (e)[0]);                                       \
                fold32((e) + 32, lid);                                                   \
                atomicAdd(&g_S[jj + 32 + lid], (e)[32]);                                 \
            }                                                                            \
        } while (0)

        // prologue tile s0 -> bufA
        MBARRIER_WAIT_PARITY(sb + ((s0 & 1) ? OFF_FULL1 : OFF_FULL0), pf[s0 & 1]);
        pf[s0 & 1] ^= 1;
        TCGEN05_FENCE_AFTER();
        LDTILE(s0 & 1, rtw, ctw, bufA);
        pa_rt = rtw; pa_ct = ctw;
        if (ctw + 1 < 64) ctw++; else { rtw++; ctw = rtw; }

        int u = s0 + 1;
        bool inA = true;                     // which buffer holds the unprocessed tile
        while (u < s1) {
            if (rtw != curband) {
                asm volatile("bar.sync 0, %0;" :: "n"(NTHREADS) : "memory");
                load_A_tmem(rtw, tA_hi, tA_lo, tid);
                asm volatile("bar.sync 1, %0;" :: "n"(NTHREADS) : "memory");
                curband = rtw;
            }
            int b2 = u & 1;
            MBARRIER_WAIT_PARITY(sb + (b2 ? OFF_FULL1 : OFF_FULL0), pf[b2]);
            pf[b2] ^= 1;
            TCGEN05_FENCE_AFTER();
            if (inA) {
                LDTILE(b2, rtw, ctw, bufB);
                pb_rt = rtw; pb_ct = ctw;
                ALUTILE(pa_rt, pa_ct, bufA);
            } else {
                LDTILE(b2, rtw, ctw, bufA);
                pa_rt = rtw; pa_ct = ctw;
                ALUTILE(pb_rt, pb_ct, bufB);
            }
            inA = !inA;
            if (ctw + 1 < 64) ctw++; else { rtw++; ctw = rtw; }
            u++;
        }
        if (inA) ALUTILE(pa_rt, pa_ct, bufA);
        else     ALUTILE(pb_rt, pb_ct, bufB);
        #undef LDTILE
        #undef ALUTILE
    }

    asm volatile("bar.sync 2, %0;" :: "n"(NTHREADS) : "memory");
    if (tid == 0) {
        MBARRIER_INVAL(sb + OFF_FULL0); MBARRIER_INVAL(sb + OFF_FULL1);
        MBARRIER_INVAL(sb + OFF_FREE0); MBARRIER_INVAL(sb + OFF_FREE1);
        MBARRIER_INVAL(sb + OFF_CPMB);
    }
    asm volatile("bar.sync 2, %0;" :: "n"(NTHREADS) : "memory");
    if (wid == 8) TCGEN05_DEALLOC(tbase, 512);
#endif  // TC_OK
}

__global__ void k_final(float* __restrict__ out) {
    __shared__ float shL[256], shW[256];
    int tid = threadIdx.x;
    float sl = 0.f, sw = 0.f;
    for (int i = tid; i < Nn; i += 256) {
        int L = g_lab[i];
        if (L != 0) {
            float cnt = (float)(g_hist[L] - 1);
            sl += logf(g_S[i]) - (g_P[i] * INV_T) / cnt;
            sw += 1.f;
        }
    }
    shL[tid] = sl; shW[tid] = sw;
    __syncthreads();
    for (int o = 128; o; o >>= 1) {
        if (tid < o) { shL[tid] += shL[tid + o]; shW[tid] += shW[tid + o]; }
        __syncthreads();
    }
    if (tid == 0) out[0] = shL[0] / shW[0];
}

extern "C" void kernel_launch(void* const* d_in, const int* in_sizes, int n_in,
                              void* d_out, int out_size) {
    (void)in_sizes; (void)n_in; (void)out_size;
    const float* feats  = (const float*)d_in[0];
    const int*   labels = (const int*)d_in[1];
    float*       out    = (float*)d_out;

    cudaFuncSetAttribute(k_main_tc, cudaFuncAttributeMaxDynamicSharedMemorySize, SMEM_SZ);

    // k_main_tc is launch #4 (ncu capture slot)
    k_zero<<<32, 256>>>();
    k_prep<<<2048, 256>>>(feats);
    k_lab<<<32, 256>>>(labels);
    k_main_tc<<<NBLK_TC, NTHREADS, SMEM_SZ>>>();
    k_csum<<<1024, 256>>>(feats);
    k_dotp<<<32, 256>>>(feats);
    k_final<<<1, 256>>>(out);
}

// round 15
// speedup vs baseline: 1.0697x; 1.0697x over previous
#include <cuda_runtime.h>
#include <cuda_bf16.h>
#include <cstdint>

// SupConLoss: N=8192 embeddings (C=128, L2-normalized), logits = X X^T / T.
// Warp-specialized tcgen05 syrk over the upper triangle (2080 tiles):
// warp 8 issues bulk-DMA + MMA chains; warps 0-7 run the exp epilogue.
// R14: 4-deep TMEM D ring (vs 2) to break the MMA<-LDTM feedback loop.
// Row + symmetric column sums per off-diag tile. P via per-class sums.

#define Nn 8192
#define TILE 128
#define TRI_TILES 2080               // 64*65/2
#define NBLK_TC 148
#define NTHREADS 288                 // 8 worker warps + 1 issuer warp
#define INV_T 14.285714285714285714f
#define PSCALE 4.5398161f            // sqrt(INV_T * log2(e))

#if !defined(__CUDA_ARCH__)
#  define TC_OK 1
#elif defined(__CUDA_ARCH_FEAT_SM103_ALL) || defined(__CUDA_ARCH_FEAT_SM100_ALL) || \
      defined(__CUDA_ARCH_FEAT_SM101_ALL) || defined(__CUDA_ARCH_FAMILY_SPECIFIC__) || \
      defined(__CUDA_ARCH_SPECIFIC__)
#  define TC_OK 1
#else
#  define TC_OK 0
#endif

__device__ uint4 g_hi[Nn * 128 / 8];   // 2 MB blocked SW128-swizzled bf16 tiles
__device__ uint4 g_lo[Nn * 128 / 8];
__device__ float g_S[Nn];
__device__ float g_P[Nn];
__device__ float g_C[4 * 128];
__device__ int   g_lab[Nn];
__device__ int   g_hist[4];

__device__ __forceinline__ uint32_t smem_u32(const void* p) {
    uint32_t a;
    asm("{ .reg .u64 t; cvta.to.shared.u64 t, %1; cvt.u32.u64 %0, t; }" : "=r"(a) : "l"(p));
    return a;
}
__device__ __forceinline__ uint32_t elect_one() {
    uint32_t pred;
    asm volatile("{ .reg .pred p; elect.sync _|p, 0xFFFFFFFF; selp.b32 %0, 1, 0, p; }" : "=r"(pred));
    return pred;
}
#define MBARRIER_INIT(mb, c) \
    asm volatile("mbarrier.init.shared.b64 [%0], %1;" :: "r"((uint32_t)(mb)), "r"((uint32_t)(c)) : "memory")
#define MBARRIER_INVAL(mb) \
    asm volatile("mbarrier.inval.shared.b64 [%0];" :: "r"((uint32_t)(mb)) : "memory")
#define MBARRIER_ARRIVE(mb) \
    asm volatile("mbarrier.arrive.release.cta.shared::cta.b64 _, [%0];" :: "r"((uint32_t)(mb)) : "memory")
#define MBARRIER_EXPECT_TX(mb, bytes) \
    asm volatile("mbarrier.arrive.expect_tx.shared.b64 _, [%0], %1;" \
                 :: "r"((uint32_t)(mb)), "r"((uint32_t)(bytes)) : "memory")
#define MBARRIER_WAIT_PARITY(mb, ph) do {                                          \
    uint32_t _m = (uint32_t)(mb), _p = (uint32_t)(ph), _d;                         \
    asm volatile("{ .reg .pred p; mbarrier.try_wait.parity.acquire.cta.shared::cta.b64 p, [%1], %2; selp.b32 %0, 1, 0, p; }" \
                 : "=r"(_d) : "r"(_m), "r"(_p) : "memory");                        \
    if (!_d) {                                                                     \
        asm volatile("{ .reg .pred P1; WL_%=: mbarrier.try_wait.parity.acquire.cta.shared::cta.b64 P1, [%0], %1, 0x989680; @P1 bra.uni WD_%=; bra.uni WL_%=; WD_%=: }" \
                     :: "r"(_m), "r"(_p) : "memory");                              \
    } } while (0)

#if TC_OK
#define TCGEN05_ALLOC(sa, n) \
    asm volatile("tcgen05.alloc.cta_group::1.sync.aligned.shared::cta.b32 [%0], %1;" \
                 :: "r"((uint32_t)(sa)), "r"((uint32_t)(n)) : "memory")
#define TCGEN05_DEALLOC(t, n) \
    asm volatile("tcgen05.dealloc.cta_group::1.sync.aligned.b32 %0, %1;" :: "r"(t), "r"((uint32_t)(n)))
#define TCGEN05_RELINQ() \
    asm volatile("tcgen05.relinquish_alloc_permit.cta_group::1.sync.aligned;")
#define TCGEN05_COMMIT(mb) \
    asm volatile("tcgen05.commit.cta_group::1.mbarrier::arrive::one.shared::cluster.b64 [%0];" \
                 :: "r"((uint32_t)(mb)) : "memory")
#define TCGEN05_WAIT_LD()      asm volatile("tcgen05.wait::ld.sync.aligned;" ::: "memory")
#define TCGEN05_FENCE_BEFORE() asm volatile("tcgen05.fence::before_thread_sync;" ::: "memory")
#define TCGEN05_FENCE_AFTER()  asm volatile("tcgen05.fence::after_thread_sync;" ::: "memory")
#define TCGEN05_LD_X32(r, a) \
    asm volatile("tcgen05.ld.sync.aligned.32x32b.x32.b32 " \
        "{%0,%1,%2,%3,%4,%5,%6,%7,%8,%9,%10,%11,%12,%13,%14,%15," \
        "%16,%17,%18,%19,%20,%21,%22,%23,%24,%25,%26,%27,%28,%29,%30,%31}, [%32];" \
        : "=r"((r)[0]),"=r"((r)[1]),"=r"((r)[2]),"=r"((r)[3]),"=r"((r)[4]),"=r"((r)[5]),"=r"((r)[6]),"=r"((r)[7]), \
          "=r"((r)[8]),"=r"((r)[9]),"=r"((r)[10]),"=r"((r)[11]),"=r"((r)[12]),"=r"((r)[13]),"=r"((r)[14]),"=r"((r)[15]), \
          "=r"((r)[16]),"=r"((r)[17]),"=r"((r)[18]),"=r"((r)[19]),"=r"((r)[20]),"=r"((r)[21]),"=r"((r)[22]),"=r"((r)[23]), \
          "=r"((r)[24]),"=r"((r)[25]),"=r"((r)[26]),"=r"((r)[27]),"=r"((r)[28]),"=r"((r)[29]),"=r"((r)[30]),"=r"((r)[31]) \
        : "r"(a))
#define BULK_G2S(dst, src, size, mb) \
    asm volatile("cp.async.bulk.shared::cluster.global.mbarrier::complete_tx::bytes [%0], [%1], %2, [%3];" \
                 :: "r"((uint32_t)(dst)), "l"(src), "r"((uint32_t)(size)), "r"((uint32_t)(mb)) : "memory")

static constexpr uint64_t SMEM_DESC_BASE_SW128 =
    (uint64_t(2) << 61) | (uint64_t(1) << 46) | (uint64_t(64) << 32) | (uint64_t(1) << 16);
#define MAKE_DESC(addr) (SMEM_DESC_BASE_SW128 | ((uint64_t)((addr) >> 4) & 0x3FFF))

#define MMA_IDESC 0x08200490u   // F32 d, BF16 a/b, M=128, N=128
static __device__ __forceinline__ void mma_ss(uint32_t d, uint64_t a, uint64_t b, uint32_t en) {
    asm volatile("{ .reg .pred p; setp.ne.u32 p, %4, 0;\n\t"
        "tcgen05.mma.cta_group::1.kind::f16 [%0], %1, %2, %3, {%5,%5,%5,%5}, p; }"
        :: "r"(d), "l"(a), "l"(b), "r"(MMA_IDESC), "r"(en), "r"(0u) : "memory");
}

// fold 32 lane-local values to per-lane column sums (proven R10/R11 pattern)
static __device__ __forceinline__ void fold32(float* e, int lid) {
    #pragma unroll
    for (int st = 0; st < 5; st++) {
        int k = 1 << st;
        int half = 32 >> (st + 1);
        int side = (lid >> st) & 1;
        #pragma unroll
        for (int j = 0; j < 16; j++) {
            if (j < half) {
                float keep = side ? e[2 * j + 1] : e[2 * j];
                float give = side ? e[2 * j] : e[2 * j + 1];
                float recv = __shfl_xor_sync(0xffffffffu, give, k);
                e[j] = keep + recv;
            }
        }
    }
}
#endif  // TC_OK

// ---- smem layout, bytes; tile bases 1024-aligned ----
#define OFF_AHI 0
#define OFF_ALO 32768
#define OFF_B0H 65536
#define OFF_B0L 98304
#define OFF_B1H 131072
#define OFF_B1L 163840
#define OFF_TP    196608
#define OFF_FULL(q) (196624 + (q) * 8)   // 4 commit mbarriers
#define OFF_FREE(q) (196656 + (q) * 8)   // 4 free mbarriers
#define OFF_CPMB  196688
#define SMEM_SZ   196704
// TMEM: 4 D buffers at cols 0, 128, 256, 384

__global__ void k_zero() {
    int i = blockIdx.x * 256 + threadIdx.x;
    if (i < Nn) g_S[i] = 0.f;
    if (i < 512) g_C[i] = 0.f;
    if (i < 4) g_hist[i] = 0;
}

// fp32 [B=4,V=2,C=128,HW=1024], PRE-SCALED by sqrt(EX2C) -> bf16 hi/lo,
// blocked SW128 tile format.
__global__ void k_prep(const float* __restrict__ f) {
    int idx = blockIdx.x * 256 + threadIdx.x;   // 524288
    int n = idx & 8191;
    int j = idx >> 13;
    int vb = n >> 10, hw = n & 1023;
    int v = vb >> 2, b = vb & 3;
    const float* base = f + b * 262144 + v * 131072 + hw;
    float x0 = base[(2 * j) * 1024] * PSCALE;
    float x1 = base[(2 * j + 1) * 1024] * PSCALE;
    __nv_bfloat16 h0 = __float2bfloat16(x0);
    __nv_bfloat16 h1 = __float2bfloat16(x1);
    __nv_bfloat16 l0 = __float2bfloat16(x0 - __bfloat162float(h0));
    __nv_bfloat16 l1 = __float2bfloat16(x1 - __bfloat162float(h1));
    uint32_t hp = (uint32_t)__bfloat16_as_ushort(h0) | ((uint32_t)__bfloat16_as_ushort(h1) << 16);
    uint32_t lp = (uint32_t)__bfloat16_as_ushort(l0) | ((uint32_t)__bfloat16_as_ushort(l1) << 16);
    int band = n >> 7, r = n & 127, k = 2 * j;
    int atom = (r >> 3) + (k >> 6) * 16;
    uint32_t byte = atom * 1024 + (r & 7) * 128 + (k & 63) * 2;
    uint32_t sw = byte ^ ((byte >> 3) & 0x70);  // SW128
    uint32_t w = band * 8192 + (sw >> 2);
    ((uint32_t*)g_hi)[w] = hp;
    ((uint32_t*)g_lo)[w] = lp;
}

__global__ void k_lab(const int* __restrict__ labels) {
    int n = blockIdx.x * 256 + threadIdx.x;
    if (n >= Nn) return;
    int vb = n >> 10;
    int v = vb >> 2, b = vb & 3;
    int L = labels[b * 2048 + v * 1024 + (n & 1023)];
    g_lab[n] = L;
    atomicAdd(&g_hist[L], 1);
}

__global__ void k_csum(const float* __restrict__ f) {
    int bid = blockIdx.x;
    int vb = bid >> 7, c = bid & 127;
    int v = vb >> 2, b = vb & 3;
    int tid = threadIdx.x;
    float4 x = ((const float4*)(f + b * 262144 + v * 131072 + c * 1024))[tid];
    int4  l = ((const int4*)(g_lab + vb * 1024))[tid];
    float s[4] = {0.f, 0.f, 0.f, 0.f};
    s[l.x] += x.x; s[l.y] += x.y; s[l.z] += x.z; s[l.w] += x.w;
    #pragma unroll
    for (int q = 0; q < 4; q++) {
        float r = s[q];
        #pragma unroll
        for (int o = 16; o; o >>= 1) r += __shfl_xor_sync(0xffffffffu, r, o);
        if ((tid & 31) == 0 && r != 0.f) atomicAdd(&g_C[q * 128 + c], r);
    }
}

__global__ void k_dotp(const float* __restrict__ f) {
    __shared__ float sC[512];
    int tid = threadIdx.x;
    int n = blockIdx.x * 256 + tid;
    int vb = n >> 10, hw = n & 1023;
    int v = vb >> 2, b = vb & 3;
    ((float2*)sC)[tid] = ((const float2*)g_C)[tid];
    __syncthreads();
    const float* base = f + b * 262144 + v * 131072 + hw;
    const float* C = sC + g_lab[n] * 128;
    float acc = 0.f;
    #pragma unroll 16
    for (int c = 0; c < 128; c++) acc = fmaf(base[c * 1024], C[c], acc);
    g_P[n] = acc - 1.f;
}

// ---- warp-specialized tcgen05 main (R11 skeleton, 4-deep TMEM D ring) ----
__global__ __launch_bounds__(NTHREADS, 1) __cluster_dims__(1, 1, 1) void k_main_tc() {
#if TC_OK
    extern __shared__ char smc[];
    uint32_t sb = smem_u32(smc);
    int tid = threadIdx.x, wid = tid >> 5, lid = tid & 31;

    if (wid == 8) TCGEN05_ALLOC(sb + OFF_TP, 512);
    else          TCGEN05_RELINQ();
    __syncthreads();
    uint32_t tbase;
    asm volatile("ld.shared.b32 %0, [%1];" : "=r"(tbase) : "r"(sb + OFF_TP));
    if (tid == 0) {
        #pragma unroll
        for (int q = 0; q < 4; q++) {
            MBARRIER_INIT(OFF_FULL(q) + sb, 1);
            MBARRIER_INIT(OFF_FREE(q) + sb, 256);
        }
        MBARRIER_INIT(sb + OFF_CPMB, 1);
    }
    __syncthreads();

    const uint32_t KOFF[8] = {0, 2, 4, 6, 1024, 1026, 1028, 1030};  // 16B units

    int s0 = (int)(((long long)blockIdx.x * TRI_TILES) / NBLK_TC);
    int s1 = (int)(((long long)(blockIdx.x + 1) * TRI_TILES) / NBLK_TC);
    int rt0 = 0;
    while ((rt0 + 1) * 64 - ((rt0 + 1) * rt0) / 2 <= s0) rt0++;
    int ct0 = rt0 + (s0 - (rt0 * 64 - (rt0 * (rt0 - 1)) / 2));

    if (wid == 8) {
        // ---------------- issuer warp ----------------
        int cp = 0, fr[4] = {0, 0, 0, 0}, fu[4] = {0, 0, 0, 0};
        int rt = rt0, ct = ct0, curA = -1;

        if (elect_one()) {      // DMA for B(s0)
            MBARRIER_EXPECT_TX(sb + OFF_CPMB, 65536);
            BULK_G2S(sb + ((s0 & 1) ? OFF_B1H : OFF_B0H), (const char*)g_hi + ct * 32768, 32768, sb + OFF_CPMB);
            BULK_G2S(sb + ((s0 & 1) ? OFF_B1L : OFF_B0L), (const char*)g_lo + ct * 32768, 32768, sb + OFF_CPMB);
        }

        for (int s = s0; s < s1; s++) {
            int b2 = s & 1, b4 = s & 3;
            if (rt != curA) {          // workers reload A then everyone syncs
                asm volatile("bar.sync 0, %0;" :: "n"(NTHREADS) : "memory");
                asm volatile("fence.proxy.async.shared::cta;" ::: "memory");
                curA = rt;
            }
            MBARRIER_WAIT_PARITY(sb + OFF_CPMB, cp);   // B(s) arrived
            cp ^= 1;
            if (s - s0 >= 4) {         // TMEM buf b4 free (epi(s-4) LDTM done)
                MBARRIER_WAIT_PARITY(OFF_FREE(b4) + sb, fr[b4]);
                fr[b4] ^= 1;
            }
            TCGEN05_FENCE_AFTER();
            if (elect_one()) {
                uint32_t dtm = tbase + b4 * 128;
                uint64_t aH = MAKE_DESC(sb + OFF_AHI);
                uint64_t aL = MAKE_DESC(sb + OFF_ALO);
                uint64_t bH = MAKE_DESC(sb + (b2 ? OFF_B1H : OFF_B0H));
                uint64_t bL = MAKE_DESC(sb + (b2 ? OFF_B1L : OFF_B0L));
                #pragma unroll
                for (int ks = 0; ks < 8; ks++) mma_ss(dtm, aH + KOFF[ks], bH + KOFF[ks], ks > 0);
                #pragma unroll
                for (int ks = 0; ks < 8; ks++) mma_ss(dtm, aH + KOFF[ks], bL + KOFF[ks], 1u);
                #pragma unroll
                for (int ks = 0; ks < 8; ks++) mma_ss(dtm, aL + KOFF[ks], bH + KOFF[ks], 1u);
                TCGEN05_COMMIT(OFF_FULL(b4) + sb);
            }
            if (s + 1 < s1) {          // prefetch B(s+1) into smem buf 1-b2
                if (s - s0 >= 1) {     // MMA(s-1) (last reader of that buf) done
                    int q = (s - 1) & 3;
                    MBARRIER_WAIT_PARITY(OFF_FULL(q) + sb, fu[q]);
                    fu[q] ^= 1;
                }
                int nct = (ct + 1 < 64) ? ct + 1 : rt + 1;
                if (elect_one()) {
                    MBARRIER_EXPECT_TX(sb + OFF_CPMB, 65536);
                    BULK_G2S(sb + ((1 - b2) ? OFF_B1H : OFF_B0H), (const char*)g_hi + nct * 32768, 32768, sb + OFF_CPMB);
                    BULK_G2S(sb + ((1 - b2) ? OFF_B1L : OFF_B0L), (const char*)g_lo + nct * 32768, 32768, sb + OFF_CPMB);
                }
            }
            if (ct + 1 < 64) ct++; else { rt++; ct = rt; }
        }
    } else {
        // ---------------- worker warps (256 threads) ----------------
        int pf[4] = {0, 0, 0, 0};
        int rt = rt0, ct = ct0, curA = -1;
        int sub = wid & 3, colh = wid >> 2;
        int row = sub * 32 + lid;

        for (int s = s0; s < s1; s++) {
            int b4 = s & 3;
            if (rt != curA) {          // reload A band, then sync with issuer
                const uint4* sH = g_hi + rt * 2048;
                const uint4* sL = g_lo + rt * 2048;
                uint4* dH = (uint4*)(smc + OFF_AHI);
                uint4* dL = (uint4*)(smc + OFF_ALO);
                for (int i = tid; i < 2048; i += 256) { dH[i] = sH[i]; dL[i] = sL[i]; }
                asm volatile("fence.proxy.async.shared::cta;" ::: "memory");
                asm volatile("bar.sync 0, %0;" :: "n"(NTHREADS) : "memory");
                curA = rt;
            }
            MBARRIER_WAIT_PARITY(OFF_FULL(b4) + sb, pf[b4]);
            pf[b4] ^= 1;
            TCGEN05_FENCE_AFTER();
            uint32_t d0[32], d1[32];
            TCGEN05_LD_X32(d0, tbase + b4 * 128 + colh * 64);
            TCGEN05_LD_X32(d1, tbase + b4 * 128 + colh * 64 + 32);
            TCGEN05_WAIT_LD();
            MBARRIER_ARRIVE(OFF_FREE(b4) + sb);   // TMEM buf free

            int gi = rt * TILE + row;
            bool diag = (rt == ct);
            int jb = ct * TILE + colh * 64;
            float S = 0.f;
            {
                float e[32];
                #pragma unroll
                for (int c = 0; c < 32; c++) {
                    float x;
                    asm("ex2.approx.ftz.f32 %0, %1;" : "=f"(x) : "f"(__uint_as_float(d0[c])));
                    e[c] = (diag && (jb + c) == gi) ? 0.f : x;
                }
                #pragma unroll
                for (int c = 0; c < 32; c++) S += e[c];
                if (!diag) {
                    fold32(e, lid);
                    atomicAdd(&g_S[jb + lid], e[0]);
                }
            }
            {
                float e[32];
                #pragma unroll
                for (int c = 0; c < 32; c++) {
                    float x;
                    asm("ex2.approx.ftz.f32 %0, %1;" : "=f"(x) : "f"(__uint_as_float(d1[c])));
                    e[c] = (diag && (jb + 32 + c) == gi) ? 0.f : x;
                }
                #pragma unroll
                for (int c = 0; c < 32; c++) S += e[c];
                if (!diag) {
                    fold32(e, lid);
                    atomicAdd(&g_S[jb + 32 + lid], e[0]);
                }
            }
            atomicAdd(&g_S[gi], S);

            if (ct + 1 < 64) ct++; else { rt++; ct = rt; }
        }
    }

    asm volatile("bar.sync 1, %0;" :: "n"(NTHREADS) : "memory");
    if (tid == 0) {
        #pragma unroll
        for (int q = 0; q < 4; q++) {
            MBARRIER_INVAL(OFF_FULL(q) + sb);
            MBARRIER_INVAL(OFF_FREE(q) + sb);
        }
        MBARRIER_INVAL(sb + OFF_CPMB);
    }
    asm volatile("bar.sync 1, %0;" :: "n"(NTHREADS) : "memory");
    if (wid == 8) TCGEN05_DEALLOC(tbase, 512);
#endif  // TC_OK
}

__global__ void k_final(float* __restrict__ out) {
    __shared__ float shL[256], shW[256];
    int tid = threadIdx.x;
    float sl = 0.f, sw = 0.f;
    for (int i = tid; i < Nn; i += 256) {
        int L = g_lab[i];
        if (L != 0) {
            float cnt = (float)(g_hist[L] - 1);
            sl += logf(g_S[i]) - (g_P[i] * INV_T) / cnt;
            sw += 1.f;
        }
    }
    shL[tid] = sl; shW[tid] = sw;
    __syncthreads();
    for (int o = 128; o; o >>= 1) {
        if (tid < o) { shL[tid] += shL[tid + o]; shW[tid] += shW[tid + o]; }
        __syncthreads();
    }
    if (tid == 0) out[0] = shL[0] / shW[0];
}

extern "C" void kernel_launch(void* const* d_in, const int* in_sizes, int n_in,
                              void* d_out, int out_size) {
    (void)in_sizes; (void)n_in; (void)out_size;
    const float* feats  = (const float*)d_in[0];
    const int*   labels = (const int*)d_in[1];
    float*       out    = (float*)d_out;

    cudaFuncSetAttribute(k_main_tc, cudaFuncAttributeMaxDynamicSharedMemorySize, SMEM_SZ);

    // k_main_tc is launch #4 (ncu capture slot)
    k_zero<<<32, 256>>>();
    k_prep<<<2048, 256>>>(feats);
    k_lab<<<32, 256>>>(labels);
    k_main_tc<<<NBLK_TC, NTHREADS, SMEM_SZ>>>();
    k_csum<<<1024, 256>>>(feats);
    k_dotp<<<32, 256>>>(feats);
    k_final<<<1, 256>>>(out);
}

// round 16
// speedup vs baseline: 1.1315x; 1.0578x over previous
#include <cuda_runtime.h>
#include <cuda_bf16.h>
#include <cstdint>

// SupConLoss: N=8192 embeddings (C=128, L2-normalized), logits = X X^T / T.
// Warp-specialized tcgen05 syrk over the upper triangle (2080 tiles):
// warp 8 issues bulk-DMA + MMA chains; warps 0-7 run the exp epilogue.
// R15: weighted tile split (band changes cost ~2 tiles) + diag-specialized
// epilogue. Row + symmetric column sums. P via per-class sums.

#define Nn 8192
#define TILE 128
#define TRI_TILES 2080               // 64*65/2
#define NBLK_TC 148
#define NTHREADS 288                 // 8 worker warps + 1 issuer warp
#define BANDW 2                     // weighted cost of a band change (tiles)
#define TOTW (TRI_TILES + 64 * BANDW)
#define INV_T 14.285714285714285714f
#define PSCALE 4.5398161f            // sqrt(INV_T * log2(e))

#if !defined(__CUDA_ARCH__)
#  define TC_OK 1
#elif defined(__CUDA_ARCH_FEAT_SM103_ALL) || defined(__CUDA_ARCH_FEAT_SM100_ALL) || \
      defined(__CUDA_ARCH_FEAT_SM101_ALL) || defined(__CUDA_ARCH_FAMILY_SPECIFIC__) || \
      defined(__CUDA_ARCH_SPECIFIC__)
#  define TC_OK 1
#else
#  define TC_OK 0
#endif

__device__ uint4 g_hi[Nn * 128 / 8];   // 2 MB blocked SW128-swizzled bf16 tiles
__device__ uint4 g_lo[Nn * 128 / 8];
__device__ float g_S[Nn];
__device__ float g_P[Nn];
__device__ float g_C[4 * 128];
__device__ int   g_lab[Nn];
__device__ int   g_hist[4];

__device__ __forceinline__ uint32_t smem_u32(const void* p) {
    uint32_t a;
    asm("{ .reg .u64 t; cvta.to.shared.u64 t, %1; cvt.u32.u64 %0, t; }" : "=r"(a) : "l"(p));
    return a;
}
__device__ __forceinline__ uint32_t elect_one() {
    uint32_t pred;
    asm volatile("{ .reg .pred p; elect.sync _|p, 0xFFFFFFFF; selp.b32 %0, 1, 0, p; }" : "=r"(pred));
    return pred;
}
#define MBARRIER_INIT(mb, c) \
    asm volatile("mbarrier.init.shared.b64 [%0], %1;" :: "r"((uint32_t)(mb)), "r"((uint32_t)(c)) : "memory")
#define MBARRIER_INVAL(mb) \
    asm volatile("mbarrier.inval.shared.b64 [%0];" :: "r"((uint32_t)(mb)) : "memory")
#define MBARRIER_ARRIVE(mb) \
    asm volatile("mbarrier.arrive.release.cta.shared::cta.b64 _, [%0];" :: "r"((uint32_t)(mb)) : "memory")
#define MBARRIER_EXPECT_TX(mb, bytes) \
    asm volatile("mbarrier.arrive.expect_tx.shared.b64 _, [%0], %1;" \
                 :: "r"((uint32_t)(mb)), "r"((uint32_t)(bytes)) : "memory")
#define MBARRIER_WAIT_PARITY(mb, ph) do {                                          \
    uint32_t _m = (uint32_t)(mb), _p = (uint32_t)(ph), _d;                         \
    asm volatile("{ .reg .pred p; mbarrier.try_wait.parity.acquire.cta.shared::cta.b64 p, [%1], %2; selp.b32 %0, 1, 0, p; }" \
                 : "=r"(_d) : "r"(_m), "r"(_p) : "memory");                        \
    if (!_d) {                                                                     \
        asm volatile("{ .reg .pred P1; WL_%=: mbarrier.try_wait.parity.acquire.cta.shared::cta.b64 P1, [%0], %1, 0x989680; @P1 bra.uni WD_%=; bra.uni WL_%=; WD_%=: }" \
                     :: "r"(_m), "r"(_p) : "memory");                              \
    } } while (0)

#if TC_OK
#define TCGEN05_ALLOC(sa, n) \
    asm volatile("tcgen05.alloc.cta_group::1.sync.aligned.shared::cta.b32 [%0], %1;" \
                 :: "r"((uint32_t)(sa)), "r"((uint32_t)(n)) : "memory")
#define TCGEN05_DEALLOC(t, n) \
    asm volatile("tcgen05.dealloc.cta_group::1.sync.aligned.b32 %0, %1;" :: "r"(t), "r"((uint32_t)(n)))
#define TCGEN05_RELINQ() \
    asm volatile("tcgen05.relinquish_alloc_permit.cta_group::1.sync.aligned;")
#define TCGEN05_COMMIT(mb) \
    asm volatile("tcgen05.commit.cta_group::1.mbarrier::arrive::one.shared::cluster.b64 [%0];" \
                 :: "r"((uint32_t)(mb)) : "memory")
#define TCGEN05_WAIT_LD()      asm volatile("tcgen05.wait::ld.sync.aligned;" ::: "memory")
#define TCGEN05_FENCE_BEFORE() asm volatile("tcgen05.fence::before_thread_sync;" ::: "memory")
#define TCGEN05_FENCE_AFTER()  asm volatile("tcgen05.fence::after_thread_sync;" ::: "memory")
#define TCGEN05_LD_X32(r, a) \
    asm volatile("tcgen05.ld.sync.aligned.32x32b.x32.b32 " \
        "{%0,%1,%2,%3,%4,%5,%6,%7,%8,%9,%10,%11,%12,%13,%14,%15," \
        "%16,%17,%18,%19,%20,%21,%22,%23,%24,%25,%26,%27,%28,%29,%30,%31}, [%32];" \
        : "=r"((r)[0]),"=r"((r)[1]),"=r"((r)[2]),"=r"((r)[3]),"=r"((r)[4]),"=r"((r)[5]),"=r"((r)[6]),"=r"((r)[7]), \
          "=r"((r)[8]),"=r"((r)[9]),"=r"((r)[10]),"=r"((r)[11]),"=r"((r)[12]),"=r"((r)[13]),"=r"((r)[14]),"=r"((r)[15]), \
          "=r"((r)[16]),"=r"((r)[17]),"=r"((r)[18]),"=r"((r)[19]),"=r"((r)[20]),"=r"((r)[21]),"=r"((r)[22]),"=r"((r)[23]), \
          "=r"((r)[24]),"=r"((r)[25]),"=r"((r)[26]),"=r"((r)[27]),"=r"((r)[28]),"=r"((r)[29]),"=r"((r)[30]),"=r"((r)[31]) \
        : "r"(a))
#define BULK_G2S(dst, src, size, mb) \
    asm volatile("cp.async.bulk.shared::cluster.global.mbarrier::complete_tx::bytes [%0], [%1], %2, [%3];" \
                 :: "r"((uint32_t)(dst)), "l"(src), "r"((uint32_t)(size)), "r"((uint32_t)(mb)) : "memory")

static constexpr uint64_t SMEM_DESC_BASE_SW128 =
    (uint64_t(2) << 61) | (uint64_t(1) << 46) | (uint64_t(64) << 32) | (uint64_t(1) << 16);
#define MAKE_DESC(addr) (SMEM_DESC_BASE_SW128 | ((uint64_t)((addr) >> 4) & 0x3FFF))

#define MMA_IDESC 0x08200490u   // F32 d, BF16 a/b, M=128, N=128
static __device__ __forceinline__ void mma_ss(uint32_t d, uint64_t a, uint64_t b, uint32_t en) {
    asm volatile("{ .reg .pred p; setp.ne.u32 p, %4, 0;\n\t"
        "tcgen05.mma.cta_group::1.kind::f16 [%0], %1, %2, %3, {%5,%5,%5,%5}, p; }"
        :: "r"(d), "l"(a), "l"(b), "r"(MMA_IDESC), "r"(en), "r"(0u) : "memory");
}

// fold 32 lane-local values to per-lane column sums (proven R10/R11 pattern)
static __device__ __forceinline__ void fold32(float* e, int lid) {
    #pragma unroll
    for (int st = 0; st < 5; st++) {
        int k = 1 << st;
        int half = 32 >> (st + 1);
        int side = (lid >> st) & 1;
        #pragma unroll
        for (int j = 0; j < 16; j++) {
            if (j < half) {
                float keep = side ? e[2 * j + 1] : e[2 * j];
                float give = side ? e[2 * j] : e[2 * j + 1];
                float recv = __shfl_xor_sync(0xffffffffu, give, k);
                e[j] = keep + recv;
            }
        }
    }
}
#endif  // TC_OK

// weighted target -> starting tile index (monotone; identical for all CTAs)
__device__ __forceinline__ int wsplit(long long k) {
    long long tgt = (k * TOTW) / NBLK_TC;
    int cum = 0, tile = 0;
    #pragma unroll 1
    for (int r = 0; r < 64; r++) {
        int L = 64 - r;
        int bw = BANDW + L;
        if (tgt < cum + bw) {
            long long off = tgt - cum;
            off = (off <= BANDW) ? 0 : off - BANDW;
            if (off > L) off = L;
            return tile + (int)off;
        }
        cum += bw; tile += L;
    }
    return TRI_TILES;
}

// ---- smem layout, bytes; tile bases 1024-aligned ----
#define OFF_AHI 0
#define OFF_ALO 32768
#define OFF_B0H 65536
#define OFF_B0L 98304
#define OFF_B1H 131072
#define OFF_B1L 163840
#define OFF_TP    196608
#define OFF_FULL0 196624
#define OFF_FULL1 196632
#define OFF_FREE0 196640
#define OFF_FREE1 196648
#define OFF_CPMB  196656
#define SMEM_SZ   196672

__global__ void k_zero() {
    int i = blockIdx.x * 256 + threadIdx.x;
    if (i < Nn) g_S[i] = 0.f;
    if (i < 512) g_C[i] = 0.f;
    if (i < 4) g_hist[i] = 0;
}

// fp32 [B=4,V=2,C=128,HW=1024], PRE-SCALED by sqrt(EX2C) -> bf16 hi/lo,
// blocked SW128 tile format.
__global__ void k_prep(const float* __restrict__ f) {
    int idx = blockIdx.x * 256 + threadIdx.x;   // 524288
    int n = idx & 8191;
    int j = idx >> 13;
    int vb = n >> 10, hw = n & 1023;
    int v = vb >> 2, b = vb & 3;
    const float* base = f + b * 262144 + v * 131072 + hw;
    float x0 = base[(2 * j) * 1024] * PSCALE;
    float x1 = base[(2 * j + 1) * 1024] * PSCALE;
    __nv_bfloat16 h0 = __float2bfloat16(x0);
    __nv_bfloat16 h1 = __float2bfloat16(x1);
    __nv_bfloat16 l0 = __float2bfloat16(x0 - __bfloat162float(h0));
    __nv_bfloat16 l1 = __float2bfloat16(x1 - __bfloat162float(h1));
    uint32_t hp = (uint32_t)__bfloat16_as_ushort(h0) | ((uint32_t)__bfloat16_as_ushort(h1) << 16);
    uint32_t lp = (uint32_t)__bfloat16_as_ushort(l0) | ((uint32_t)__bfloat16_as_ushort(l1) << 16);
    int band = n >> 7, r = n & 127, k = 2 * j;
    int atom = (r >> 3) + (k >> 6) * 16;
    uint32_t byte = atom * 1024 + (r & 7) * 128 + (k & 63) * 2;
    uint32_t sw = byte ^ ((byte >> 3) & 0x70);  // SW128
    uint32_t w = band * 8192 + (sw >> 2);
    ((uint32_t*)g_hi)[w] = hp;
    ((uint32_t*)g_lo)[w] = lp;
}

__global__ void k_lab(const int* __restrict__ labels) {
    int n = blockIdx.x * 256 + threadIdx.x;
    if (n >= Nn) return;
    int vb = n >> 10;
    int v = vb >> 2, b = vb & 3;
    int L = labels[b * 2048 + v * 1024 + (n & 1023)];
    g_lab[n] = L;
    atomicAdd(&g_hist[L], 1);
}

__global__ void k_csum(const float* __restrict__ f) {
    int bid = blockIdx.x;
    int vb = bid >> 7, c = bid & 127;
    int v = vb >> 2, b = vb & 3;
    int tid = threadIdx.x;
    float4 x = ((const float4*)(f + b * 262144 + v * 131072 + c * 1024))[tid];
    int4  l = ((const int4*)(g_lab + vb * 1024))[tid];
    float s[4] = {0.f, 0.f, 0.f, 0.f};
    s[l.x] += x.x; s[l.y] += x.y; s[l.z] += x.z; s[l.w] += x.w;
    #pragma unroll
    for (int q = 0; q < 4; q++) {
        float r = s[q];
        #pragma unroll
        for (int o = 16; o; o >>= 1) r += __shfl_xor_sync(0xffffffffu, r, o);
        if ((tid & 31) == 0 && r != 0.f) atomicAdd(&g_C[q * 128 + c], r);
    }
}

__global__ void k_dotp(const float* __restrict__ f) {
    __shared__ float sC[512];
    int tid = threadIdx.x;
    int n = blockIdx.x * 256 + tid;
    int vb = n >> 10, hw = n & 1023;
    int v = vb >> 2, b = vb & 3;
    ((float2*)sC)[tid] = ((const float2*)g_C)[tid];
    __syncthreads();
    const float* base = f + b * 262144 + v * 131072 + hw;
    const float* C = sC + g_lab[n] * 128;
    float acc = 0.f;
    #pragma unroll 16
    for (int c = 0; c < 128; c++) acc = fmaf(base[c * 1024], C[c], acc);
    g_P[n] = acc - 1.f;
}

// ---- warp-specialized tcgen05 main (R11 skeleton + weighted split) ----
__global__ __launch_bounds__(NTHREADS, 1) __cluster_dims__(1, 1, 1) void k_main_tc() {
#if TC_OK
    extern __shared__ char smc[];
    uint32_t sb = smem_u32(smc);
    int tid = threadIdx.x, wid = tid >> 5, lid = tid & 31;

    if (wid == 8) TCGEN05_ALLOC(sb + OFF_TP, 512);
    else          TCGEN05_RELINQ();
    __syncthreads();
    uint32_t tbase;
    asm volatile("ld.shared.b32 %0, [%1];" : "=r"(tbase) : "r"(sb + OFF_TP));
    if (tid == 0) {
        MBARRIER_INIT(sb + OFF_FULL0, 1);
        MBARRIER_INIT(sb + OFF_FULL1, 1);
        MBARRIER_INIT(sb + OFF_FREE0, 256);
        MBARRIER_INIT(sb + OFF_FREE1, 256);
        MBARRIER_INIT(sb + OFF_CPMB, 1);
    }
    __syncthreads();

    const uint32_t KOFF[8] = {0, 2, 4, 6, 1024, 1026, 1028, 1030};  // 16B units

    int s0 = wsplit(blockIdx.x);
    int s1 = wsplit(blockIdx.x + 1);
    if (s0 >= s1) {   // empty range: skip pipeline, go to cleanup barriers
        asm volatile("bar.sync 1, %0;" :: "n"(NTHREADS) : "memory");
        if (tid == 0) {
            MBARRIER_INVAL(sb + OFF_FULL0); MBARRIER_INVAL(sb + OFF_FULL1);
            MBARRIER_INVAL(sb + OFF_FREE0); MBARRIER_INVAL(sb + OFF_FREE1);
            MBARRIER_INVAL(sb + OFF_CPMB);
        }
        asm volatile("bar.sync 1, %0;" :: "n"(NTHREADS) : "memory");
        if (wid == 8) TCGEN05_DEALLOC(tbase, 512);
        return;
    }
    int rt0 = 0;
    while ((rt0 + 1) * 64 - ((rt0 + 1) * rt0) / 2 <= s0) rt0++;
    int ct0 = rt0 + (s0 - (rt0 * 64 - (rt0 * (rt0 - 1)) / 2));

    if (wid == 8) {
        // ---------------- issuer warp ----------------
        int cp = 0, fr[2] = {0, 0}, fu[2] = {0, 0};
        int rt = rt0, ct = ct0, curA = -1;

        if (elect_one()) {      // DMA for B(s0)
            MBARRIER_EXPECT_TX(sb + OFF_CPMB, 65536);
            BULK_G2S(sb + ((s0 & 1) ? OFF_B1H : OFF_B0H), (const char*)g_hi + ct * 32768, 32768, sb + OFF_CPMB);
            BULK_G2S(sb + ((s0 & 1) ? OFF_B1L : OFF_B0L), (const char*)g_lo + ct * 32768, 32768, sb + OFF_CPMB);
        }

        for (int s = s0; s < s1; s++) {
            int b = s & 1;
            if (rt != curA) {          // workers reload A then everyone syncs
                asm volatile("bar.sync 0, %0;" :: "n"(NTHREADS) : "memory");
                asm volatile("fence.proxy.async.shared::cta;" ::: "memory");
                curA = rt;
            }
            MBARRIER_WAIT_PARITY(sb + OFF_CPMB, cp);   // B(s) arrived
            cp ^= 1;
            if (s - s0 >= 2) {         // TMEM buf b free (epi(s-2) LDTM done)
                MBARRIER_WAIT_PARITY(sb + (b ? OFF_FREE1 : OFF_FREE0), fr[b]);
                fr[b] ^= 1;
            }
            TCGEN05_FENCE_AFTER();
            if (elect_one()) {
                uint32_t dtm = tbase + b * 128;
                uint64_t aH = MAKE_DESC(sb + OFF_AHI);
                uint64_t aL = MAKE_DESC(sb + OFF_ALO);
                uint64_t bH = MAKE_DESC(sb + (b ? OFF_B1H : OFF_B0H));
                uint64_t bL = MAKE_DESC(sb + (b ? OFF_B1L : OFF_B0L));
                #pragma unroll
                for (int ks = 0; ks < 8; ks++) mma_ss(dtm, aH + KOFF[ks], bH + KOFF[ks], ks > 0);
                #pragma unroll
                for (int ks = 0; ks < 8; ks++) mma_ss(dtm, aH + KOFF[ks], bL + KOFF[ks], 1u);
                #pragma unroll
                for (int ks = 0; ks < 8; ks++) mma_ss(dtm, aL + KOFF[ks], bH + KOFF[ks], 1u);
                TCGEN05_COMMIT(sb + (b ? OFF_FULL1 : OFF_FULL0));
            }
            if (s + 1 < s1) {          // prefetch B(s+1) into buf 1-b
                if (s - s0 >= 1) {     // MMA(s-1) (last reader of buf 1-b) done
                    MBARRIER_WAIT_PARITY(sb + ((1 - b) ? OFF_FULL1 : OFF_FULL0), fu[1 - b]);
                    fu[1 - b] ^= 1;
                }
                int nct = (ct + 1 < 64) ? ct + 1 : rt + 1;
                if (elect_one()) {
                    MBARRIER_EXPECT_TX(sb + OFF_CPMB, 65536);
                    BULK_G2S(sb + ((1 - b) ? OFF_B1H : OFF_B0H), (const char*)g_hi + nct * 32768, 32768, sb + OFF_CPMB);
                    BULK_G2S(sb + ((1 - b) ? OFF_B1L : OFF_B0L), (const char*)g_lo + nct * 32768, 32768, sb + OFF_CPMB);
                }
            }
            if (ct + 1 < 64) ct++; else { rt++; ct = rt; }
        }
    } else {
        // ---------------- worker warps (256 threads) ----------------
        int pf[2] = {0, 0};
        int rt = rt0, ct = ct0, curA = -1;
        int sub = wid & 3, colh = wid >> 2;
        int row = sub * 32 + lid;

        for (int s = s0; s < s1; s++) {
            int b = s & 1;
            if (rt != curA) {          // reload A band, then sync with issuer
                const uint4* sH = g_hi + rt * 2048;
                const uint4* sL = g_lo + rt * 2048;
                uint4* dH = (uint4*)(smc + OFF_AHI);
                uint4* dL = (uint4*)(smc + OFF_ALO);
                for (int i = tid; i < 2048; i += 256) { dH[i] = sH[i]; dL[i] = sL[i]; }
                asm volatile("fence.proxy.async.shared::cta;" ::: "memory");
                asm volatile("bar.sync 0, %0;" :: "n"(NTHREADS) : "memory");
                curA = rt;
            }
            MBARRIER_WAIT_PARITY(sb + (b ? OFF_FULL1 : OFF_FULL0), pf[b]);
            pf[b] ^= 1;
            TCGEN05_FENCE_AFTER();
            uint32_t d0[32], d1[32];
            TCGEN05_LD_X32(d0, tbase + b * 128 + colh * 64);
            TCGEN05_LD_X32(d1, tbase + b * 128 + colh * 64 + 32);
            TCGEN05_WAIT_LD();
            MBARRIER_ARRIVE(sb + (b ? OFF_FREE1 : OFF_FREE0));  // TMEM buf free

            int gi = rt * TILE + row;
            int jb = ct * TILE + colh * 64;
            float S = 0.f;
            if (rt != ct) {            // off-diagonal: no mask SEL, fold cols
                float e[32];
                #pragma unroll
                for (int c = 0; c < 32; c++) {
                    asm("ex2.approx.ftz.f32 %0, %1;" : "=f"(e[c]) : "f"(__uint_as_float(d0[c])));
                }
                #pragma unroll
                for (int c = 0; c < 32; c++) S += e[c];
                fold32(e, lid);
                atomicAdd(&g_S[jb + lid], e[0]);
                #pragma unroll
                for (int c = 0; c < 32; c++) {
                    asm("ex2.approx.ftz.f32 %0, %1;" : "=f"(e[c]) : "f"(__uint_as_float(d1[c])));
                }
                #pragma unroll
                for (int c = 0; c < 32; c++) S += e[c];
                fold32(e, lid);
                atomicAdd(&g_S[jb + 32 + lid], e[0]);
            } else {                   // diagonal: mask j==i, rows only
                #pragma unroll
                for (int c = 0; c < 32; c++) {
                    float x;
                    asm("ex2.approx.ftz.f32 %0, %1;" : "=f"(x) : "f"(__uint_as_float(d0[c])));
                    if ((jb + c) != gi) S += x;
                }
                #pragma unroll
                for (int c = 0; c < 32; c++) {
                    float x;
                    asm("ex2.approx.ftz.f32 %0, %1;" : "=f"(x) : "f"(__uint_as_float(d1[c])));
                    if ((jb + 32 + c) != gi) S += x;
                }
            }
            atomicAdd(&g_S[gi], S);

            if (ct + 1 < 64) ct++; else { rt++; ct = rt; }
        }
    }

    asm volatile("bar.sync 1, %0;" :: "n"(NTHREADS) : "memory");
    if (tid == 0) {
        MBARRIER_INVAL(sb + OFF_FULL0); MBARRIER_INVAL(sb + OFF_FULL1);
        MBARRIER_INVAL(sb + OFF_FREE0); MBARRIER_INVAL(sb + OFF_FREE1);
        MBARRIER_INVAL(sb + OFF_CPMB);
    }
    asm volatile("bar.sync 1, %0;" :: "n"(NTHREADS) : "memory");
    if (wid == 8) TCGEN05_DEALLOC(tbase, 512);
#endif  // TC_OK
}

__global__ void k_final(float* __restrict__ out) {
    __shared__ float shL[256], shW[256];
    int tid = threadIdx.x;
    float sl = 0.f, sw = 0.f;
    for (int i = tid; i < Nn; i += 256) {
        int L = g_lab[i];
        if (L != 0) {
            float cnt = (float)(g_hist[L] - 1);
            sl += logf(g_S[i]) - (g_P[i] * INV_T) / cnt;
            sw += 1.f;
        }
    }
    shL[tid] = sl; shW[tid] = sw;
    __syncthreads();
    for (int o = 128; o; o >>= 1) {
        if (tid < o) { shL[tid] += shL[tid + o]; shW[tid] += shW[tid + o]; }
        __syncthreads();
    }
    if (tid == 0) out[0] = shL[0] / shW[0];
}

extern "C" void kernel_launch(void* const* d_in, const int* in_sizes, int n_in,
                              void* d_out, int out_size) {
    (void)in_sizes; (void)n_in; (void)out_size;
    const float* feats  = (const float*)d_in[0];
    const int*   labels = (const int*)d_in[1];
    float*       out    = (float*)d_out;

    cudaFuncSetAttribute(k_main_tc, cudaFuncAttributeMaxDynamicSharedMemorySize, SMEM_SZ);

    k_zero<<<32, 256>>>();
    k_prep<<<2048, 256>>>(feats);
    k_lab<<<32, 256>>>(labels);
    k_main_tc<<<NBLK_TC, NTHREADS, SMEM_SZ>>>();
    k_csum<<<1024, 256>>>(feats);
    k_dotp<<<32, 256>>>(feats);
    k_final<<<1, 256>>>(out);
}